// round 16
// baseline (speedup 1.0000x reference)
#include <cuda_runtime.h>
#include <cuda_bf16.h>
#include <cuda_fp16.h>
#include <stdint.h>

#define NN   100000
#define NE   1600000
#define INF  256
#define OUTF 64
#define SCAN_B 512
#define NB_SCAN ((NN + SCAN_B - 1) / SCAN_B)   // 196
#define TM 128
#define NKSTEP (INF / 16)                      // 16
#define NGEMMB ((NN + TM - 1) / TM)            // 782
#define NZEROB ((NN + 255) / 256)              // 391
#define NPREPB ((NKSTEP * 8 * 32 + 255) / 256) // 16

// ---------------- scratch (device globals; no allocations allowed) ----------
__device__ int   g_deg[NN];
__device__ int   g_rowptr[NN + 1];
__device__ int   g_cursor[NN];
__device__ int2  g_csr[NE];                 // {src, float_as_int(w)}
__device__ int   g_bsum[NB_SCAN];
// W bf16 hi/lo packed in mma.m16n8k16 B-fragment layout
__device__ uint2 g_Bh[NKSTEP * 8 * 32];
__device__ uint2 g_Bl[NKSTEP * 8 * 32];
// fp16 feature ping-pong buffers: [node][feat-pair] (128B per node row)
__device__ __align__(16) __half2 g_hbuf0[(size_t)NN * 32];
__device__ __align__(16) __half2 g_hbuf1[(size_t)NN * 32];

// ---------------- helpers ----------------------------------------------------
__device__ __forceinline__ void split_pack(float a, float b, uint32_t& hi, uint32_t& lo) {
    __nv_bfloat16 h0 = __float2bfloat16(a);
    __nv_bfloat16 h1 = __float2bfloat16(b);
    __nv_bfloat16 l0 = __float2bfloat16(a - __bfloat162float(h0));
    __nv_bfloat16 l1 = __float2bfloat16(b - __bfloat162float(h1));
    __nv_bfloat162 hp(h0, h1), lp(l0, l1);
    hi = *(uint32_t*)&hp;
    lo = *(uint32_t*)&lp;
}

__device__ __forceinline__ void hmma(float* c, const uint32_t* a, const uint2 b) {
    asm volatile(
        "mma.sync.aligned.m16n8k16.row.col.f32.bf16.bf16.f32 "
        "{%0,%1,%2,%3}, {%4,%5,%6,%7}, {%8,%9}, {%0,%1,%2,%3};"
        : "+f"(c[0]), "+f"(c[1]), "+f"(c[2]), "+f"(c[3])
        : "r"(a[0]), "r"(a[1]), "r"(a[2]), "r"(a[3]), "r"(b.x), "r"(b.y));
}

// ---------------- init: zero degrees + pack W fragments (fused) --------------
__global__ void k_init(const float* __restrict__ W) {
    int bid = blockIdx.x;
    int tid = threadIdx.x;
    if (bid < NZEROB) {
        int i = bid * 256 + tid;
        if (i < NN) g_deg[i] = 0;
    } else {
        int i = (bid - NZEROB) * 256 + tid;
        if (i >= NKSTEP * 8 * 32) return;
        int lane = i & 31;
        int nblk = (i >> 5) & 7;
        int ks   = i >> 8;
        int n  = nblk * 8 + (lane >> 2);
        int k0 = ks * 16 + (lane & 3) * 2;
        const float* wr = W + (size_t)n * INF;
        uint32_t h0, l0, h1, l1;
        split_pack(wr[k0],     wr[k0 + 1], h0, l0);
        split_pack(wr[k0 + 8], wr[k0 + 9], h1, l1);
        g_Bh[i] = make_uint2(h0, h1);
        g_Bl[i] = make_uint2(l0, l1);
    }
}

// ---------------- CSR build --------------------------------------------------
__global__ void k_hist(const int* __restrict__ dst, int E) {
    int e = blockIdx.x * blockDim.x + threadIdx.x;
    if (e < E) atomicAdd(&g_deg[dst[e]], 1);
}

__global__ void k_blocksum() {
    __shared__ int red[SCAN_B];
    int t = threadIdx.x;
    int i = blockIdx.x * SCAN_B + t;
    red[t] = (i < NN) ? g_deg[i] : 0;
    __syncthreads();
#pragma unroll
    for (int off = SCAN_B / 2; off > 0; off >>= 1) {
        if (t < off) red[t] += red[t + off];
        __syncthreads();
    }
    if (t == 0) g_bsum[blockIdx.x] = red[0];
}

__global__ void k_fill() {
    __shared__ int s[SCAN_B];
    int t = threadIdx.x;
    int bid = blockIdx.x;
    int part = 0;
    for (int j = t; j < bid; j += SCAN_B) part += g_bsum[j];
    s[t] = part;
    __syncthreads();
#pragma unroll
    for (int off = SCAN_B / 2; off > 0; off >>= 1) {
        if (t < off) s[t] += s[t + off];
        __syncthreads();
    }
    int base = s[0];
    __syncthreads();
    int i = bid * SCAN_B + t;
    int v = (i < NN) ? g_deg[i] : 0;
    s[t] = v;
    __syncthreads();
#pragma unroll
    for (int off = 1; off < SCAN_B; off <<= 1) {
        int u = (t >= off) ? s[t - off] : 0;
        __syncthreads();
        s[t] += u;
        __syncthreads();
    }
    if (i < NN) {
        int p = base + s[t] - v;
        g_rowptr[i] = p;
        g_cursor[i] = p;
    }
    if (bid == NB_SCAN - 1 && t == SCAN_B - 1)
        g_rowptr[NN] = base + s[t];
}

// ---------------- fused tensor-core GEMM + edge scatter ----------------------
__global__ void __launch_bounds__(256)
k_gemm_scatter(const float* __restrict__ x, const float* __restrict__ bias, int M,
               const int* __restrict__ src, const int* __restrict__ dst,
               const float* __restrict__ w, int E) {
    const int tid  = threadIdx.x;
    if (blockIdx.x >= NGEMMB) {
        int e = (blockIdx.x - NGEMMB) * 256 + tid;
        if (e < E) {
            int d = dst[e];
            int p = atomicAdd(&g_cursor[d], 1);
            g_csr[p] = make_int2(src[e], __float_as_int(w[e]));
        }
        return;
    }

    const int wid  = tid >> 5;
    const int lane = tid & 31;
    const int warp_m = wid & 3;
    const int warp_n = wid >> 2;
    const int m0 = blockIdx.x * TM + warp_m * 32;

    const int qr = lane >> 2;
    const int qc = (lane & 3) * 2;

    float c[2][4][4];
#pragma unroll
    for (int mf = 0; mf < 2; ++mf)
#pragma unroll
        for (int nf = 0; nf < 4; ++nf)
#pragma unroll
            for (int j = 0; j < 4; ++j) c[mf][nf][j] = 0.f;

    const float* xp[2][2];
    bool vld[2][2];
#pragma unroll
    for (int mf = 0; mf < 2; ++mf)
#pragma unroll
        for (int h = 0; h < 2; ++h) {
            int r = m0 + mf * 16 + h * 8 + qr;
            vld[mf][h] = (r < M);
            xp[mf][h] = x + (size_t)(vld[mf][h] ? r : 0) * INF;
        }

    const int bbase = warp_n * 4;

    for (int ks = 0; ks < NKSTEP; ++ks) {
        const int k0 = ks * 16 + qc;
        uint32_t ah[2][4], al[2][4];
#pragma unroll
        for (int mf = 0; mf < 2; ++mf) {
            float2 p00 = vld[mf][0] ? *(const float2*)(xp[mf][0] + k0)     : make_float2(0.f, 0.f);
            float2 p02 = vld[mf][0] ? *(const float2*)(xp[mf][0] + k0 + 8) : make_float2(0.f, 0.f);
            float2 p10 = vld[mf][1] ? *(const float2*)(xp[mf][1] + k0)     : make_float2(0.f, 0.f);
            float2 p12 = vld[mf][1] ? *(const float2*)(xp[mf][1] + k0 + 8) : make_float2(0.f, 0.f);
            split_pack(p00.x, p00.y, ah[mf][0], al[mf][0]);
            split_pack(p10.x, p10.y, ah[mf][1], al[mf][1]);
            split_pack(p02.x, p02.y, ah[mf][2], al[mf][2]);
            split_pack(p12.x, p12.y, ah[mf][3], al[mf][3]);
        }
        uint2 bh[4], bl[4];
#pragma unroll
        for (int nf = 0; nf < 4; ++nf) {
            int idx = (ks * 8 + bbase + nf) * 32 + lane;
            bh[nf] = g_Bh[idx];
            bl[nf] = g_Bl[idx];
        }
#pragma unroll
        for (int mf = 0; mf < 2; ++mf)
#pragma unroll
            for (int nf = 0; nf < 4; ++nf) {
                hmma(c[mf][nf], ah[mf], bh[nf]);
                hmma(c[mf][nf], ah[mf], bl[nf]);
                hmma(c[mf][nf], al[mf], bh[nf]);
            }
    }

    // epilogue: add bias, convert to fp16, store to g_hbuf0
#pragma unroll
    for (int mf = 0; mf < 2; ++mf) {
        int r0 = m0 + mf * 16 + qr;
#pragma unroll
        for (int nf = 0; nf < 4; ++nf) {
            int col = warp_n * 32 + nf * 8 + qc;     // even
            float bx = __ldg(&bias[col]);
            float by = __ldg(&bias[col + 1]);
            if (r0 < M)
                g_hbuf0[(size_t)r0 * 32 + (col >> 1)] =
                    __floats2half2_rn(c[mf][nf][0] + bx, c[mf][nf][1] + by);
            if (r0 + 8 < M)
                g_hbuf0[(size_t)(r0 + 8) * 32 + (col >> 1)] =
                    __floats2half2_rn(c[mf][nf][2] + bx, c[mf][nf][3] + by);
        }
    }
}

// ---------------- SpMM hop: 4 edges per warp step ----------------------------
// warp = 1 node. lane: g = lane>>3 (edge subgroup 0..3), s = lane&7 (16B slice).
// Per step, group g handles edge e+g: 1 meta LDG.64 + 1 row-gather LDG.128 per
// warp serve 4 edges. Partial sums folded across groups by xor-shuffle {8,16}.
__global__ void k_spmm(int insel, int outsel, float* __restrict__ dout) {
    const uint4* __restrict__ in =
        (insel == 0) ? (const uint4*)g_hbuf0 : (const uint4*)g_hbuf1;

    int node = blockIdx.x * 8 + threadIdx.y;
    if (node >= NN) return;
    const int lane = threadIdx.x;
    const int g = lane >> 3;
    const int s = lane & 7;
    const int beg = __ldg(&g_rowptr[node]);
    const int end = __ldg(&g_rowptr[node + 1]);

    float2 a0 = make_float2(0.f, 0.f), a1 = a0, a2 = a0, a3 = a0;

    int e = beg;
    // unrolled: 8 edges per iteration (2 independent meta->gather chains)
    for (; e + 8 <= end; e += 8) {
        int2 mA = __ldg(&g_csr[e + g]);
        int2 mB = __ldg(&g_csr[e + 4 + g]);
        uint4 dA = __ldg(&in[(size_t)mA.x * 8 + s]);
        uint4 dB = __ldg(&in[(size_t)mB.x * 8 + s]);
        float wA = __int_as_float(mA.y);
        float wB = __int_as_float(mB.y);
        float2 f;
        f = __half22float2(*(__half2*)&dA.x); a0.x += wA * f.x; a0.y += wA * f.y;
        f = __half22float2(*(__half2*)&dA.y); a1.x += wA * f.x; a1.y += wA * f.y;
        f = __half22float2(*(__half2*)&dA.z); a2.x += wA * f.x; a2.y += wA * f.y;
        f = __half22float2(*(__half2*)&dA.w); a3.x += wA * f.x; a3.y += wA * f.y;
        f = __half22float2(*(__half2*)&dB.x); a0.x += wB * f.x; a0.y += wB * f.y;
        f = __half22float2(*(__half2*)&dB.y); a1.x += wB * f.x; a1.y += wB * f.y;
        f = __half22float2(*(__half2*)&dB.z); a2.x += wB * f.x; a2.y += wB * f.y;
        f = __half22float2(*(__half2*)&dB.w); a3.x += wB * f.x; a3.y += wB * f.y;
    }
    // tail: 4 edges per step with per-group guard
    for (; e < end; e += 4) {
        int eg = e + g;
        bool v = (eg < end);
        int2 m = __ldg(&g_csr[v ? eg : beg]);
        float w = v ? __int_as_float(m.y) : 0.f;
        uint4 d = __ldg(&in[(size_t)m.x * 8 + s]);
        float2 f;
        f = __half22float2(*(__half2*)&d.x); a0.x += w * f.x; a0.y += w * f.y;
        f = __half22float2(*(__half2*)&d.y); a1.x += w * f.x; a1.y += w * f.y;
        f = __half22float2(*(__half2*)&d.z); a2.x += w * f.x; a2.y += w * f.y;
        f = __half22float2(*(__half2*)&d.w); a3.x += w * f.x; a3.y += w * f.y;
    }

    // fold the 4 edge-groups (xor over lane bits 8 and 16)
#pragma unroll
    for (int off = 8; off < 32; off <<= 1) {
        a0.x += __shfl_xor_sync(0xFFFFFFFF, a0.x, off);
        a0.y += __shfl_xor_sync(0xFFFFFFFF, a0.y, off);
        a1.x += __shfl_xor_sync(0xFFFFFFFF, a1.x, off);
        a1.y += __shfl_xor_sync(0xFFFFFFFF, a1.y, off);
        a2.x += __shfl_xor_sync(0xFFFFFFFF, a2.x, off);
        a2.y += __shfl_xor_sync(0xFFFFFFFF, a2.y, off);
        a3.x += __shfl_xor_sync(0xFFFFFFFF, a3.x, off);
        a3.y += __shfl_xor_sync(0xFFFFFFFF, a3.y, off);
    }

    if (g == 0) {
        if (outsel == 2) {
            float4* dst = (float4*)&dout[(size_t)node * OUTF + s * 8];
            dst[0] = make_float4(a0.x, a0.y, a1.x, a1.y);
            dst[1] = make_float4(a2.x, a2.y, a3.x, a3.y);
        } else {
            uint4* out = (outsel == 0) ? (uint4*)g_hbuf0 : (uint4*)g_hbuf1;
            __half2 h0 = __floats2half2_rn(a0.x, a0.y);
            __half2 h1 = __floats2half2_rn(a1.x, a1.y);
            __half2 h2 = __floats2half2_rn(a2.x, a2.y);
            __half2 h3 = __floats2half2_rn(a3.x, a3.y);
            out[(size_t)node * 8 + s] =
                make_uint4(*(uint32_t*)&h0, *(uint32_t*)&h1,
                           *(uint32_t*)&h2, *(uint32_t*)&h3);
        }
    }
}

// ---------------- launch -----------------------------------------------------
extern "C" void kernel_launch(void* const* d_in, const int* in_sizes, int n_in,
                              void* d_out, int out_size) {
    const float* x    = (const float*)d_in[0];
    const float* W    = (const float*)d_in[1];
    const float* bias = (const float*)d_in[2];
    const int*   esrc = (const int*)d_in[3];
    const int*   edst = (const int*)d_in[4];
    const float* ew   = (const float*)d_in[5];
    float* out = (float*)d_out;

    const int M = in_sizes[0] / INF;      // 100000
    const int E = in_sizes[3];            // 1600000

    // init: zero degrees + pack W fragments
    k_init<<<NZEROB + NPREPB, 256>>>(W);
    // CSR build
    k_hist<<<(E + 255) / 256, 256>>>(edst, E);
    k_blocksum<<<NB_SCAN, SCAN_B>>>();
    k_fill<<<NB_SCAN, SCAN_B>>>();
    // fused GEMM (blocks 0..781) + scatter (rest) -> g_hbuf0
    k_gemm_scatter<<<NGEMMB + (E + 255) / 256, 256>>>(x, bias, M, esrc, edst, ew, E);
    // 3 hops: hbuf0 -> hbuf1 -> hbuf0 -> d_out
    dim3 bt(32, 8);
    int nblk = (NN + 7) / 8;
    k_spmm<<<nblk, bt>>>(0, 1, out);
    k_spmm<<<nblk, bt>>>(1, 0, out);
    k_spmm<<<nblk, bt>>>(0, 2, out);
    (void)n_in; (void)out_size;
}